// round 16
// baseline (speedup 1.0000x reference)
#include <cuda_runtime.h>
#include <math.h>

#define BB 8
#define NN 4096
#define CC 64
#define NPOINT 1024
#define KK 32
#define MM (BB*NPOINT)
#define RR (MM*KK)          /* 262144 gathered rows */
#define UR (BB*NN)          /* 32768 unique rows    */
#define EPSBN 1e-5f
#define SLOPE 0.1f

typedef unsigned long long u64;

__device__ float g_buf[4][UR*CC];      // 0:y_t 1:y1/y3->x1 2:y2 3:y4
__device__ int   g_fps[MM];
__device__ int   g_knn[RR];
__device__ float g_pn[BB*NN];
__device__ int   g_cnt[UR];
__device__ float g_part[256][2][CC];
__device__ float g_aff[5][2][CC];
__device__ int   g_cellcnt[BB*512];
__device__ int   g_cellbase[BB*512];
__device__ int   g_ckey[UR];
__device__ int   g_perm[UR];

__device__ __forceinline__ float leaky(float x){ return x>=0.f ? x : SLOPE*x; }

// ---- packed f32x2 (bitwise == two scalar rn ops) ----
#define ADD2(o,a,b) asm("add.rn.f32x2 %0,%1,%2;":"=l"(o):"l"(a),"l"(b))
#define MUL2(o,a,b) asm("mul.rn.f32x2 %0,%1,%2;":"=l"(o):"l"(a),"l"(b))
#define PACK2(o,lo,hi) asm("mov.b64 %0,{%1,%2};":"=l"(o):"f"(lo),"f"(hi))
#define UNPK2(lo,hi,i) asm("mov.b64 {%0,%1},%2;":"=f"(lo),"=f"(hi):"l"(i))

// ---------------- prep: pnorm + zero counters ----------------
__global__ void prep_kernel(const float* __restrict__ xyz){
    int i = blockIdx.x*blockDim.x + threadIdx.x;
    if (i < UR){
        float x = xyz[3*i], y = xyz[3*i+1], z = xyz[3*i+2];
        g_pn[i] = __fadd_rn(__fadd_rn(__fmul_rn(x,x), __fmul_rn(y,y)), __fmul_rn(z,z));
        g_cnt[i] = 0;
    }
    if (i < BB*512) g_cellcnt[i] = 0;
}

// ---------------- spatial sort (8^3 morton counting sort) ----------------
__global__ void cellkey_kernel(const float* __restrict__ xyz){
    int i = blockIdx.x*blockDim.x + threadIdx.x;
    if (i >= UR) return;
    int b = i >> 12;
    float x = xyz[3*i], y = xyz[3*i+1], z = xyz[3*i+2];
    int ix = min(7, max(0, (int)((x + 4.5f) * (8.0f/9.0f))));
    int iy = min(7, max(0, (int)((y + 4.5f) * (8.0f/9.0f))));
    int iz = min(7, max(0, (int)((z + 4.5f) * (8.0f/9.0f))));
    int m = 0;
#pragma unroll
    for (int j=0;j<3;++j)
        m |= ((ix>>j&1)<<(3*j)) | ((iy>>j&1)<<(3*j+1)) | ((iz>>j&1)<<(3*j+2));
    int rank = atomicAdd(&g_cellcnt[(b<<9)+m], 1);
    g_ckey[i] = m | (rank<<9);
}
__global__ void __launch_bounds__(512)
scan_kernel(){
    __shared__ int s[512];
    int b = blockIdx.x, t = threadIdx.x;
    int v = g_cellcnt[(b<<9)+t];
    s[t] = v; __syncthreads();
    int acc = v;
    for (int off=1; off<512; off<<=1){
        int add = (t >= off) ? s[t-off] : 0;
        __syncthreads();
        acc += add; s[t] = acc;
        __syncthreads();
    }
    g_cellbase[(b<<9)+t] = acc - v;   // exclusive
}
__global__ void scatter_kernel(){
    int i = blockIdx.x*blockDim.x + threadIdx.x;
    if (i >= UR) return;
    int b = i >> 12;
    int ck = g_ckey[i];
    int cell = ck & 511, rank = ck >> 9;
    g_perm[(b<<12) + g_cellbase[(b<<9)+cell] + rank] = i & 4095;
}

// ---------------- FPS: pruned-exact, 1 block/batch, 512 thr, 8 pts ------
// Warp = 256 spatially-contiguous points with bounding sphere (m,r).
// Skip a warp's update when |c-m| >= r + sqrt(warp max dist) (conservative
// fp margins) -- provably a no-op on every dist in the warp, so the cached
// warp argmax key remains exact. Distance math = bit-exact reference order.
__global__ void __launch_bounds__(512)
fps_kernel(const float* __restrict__ xyz, float* __restrict__ out){
    __shared__ u64 swk[2][16];
    int b=blockIdx.x, tid=threadIdx.x, lane=tid&31, wid=tid>>5;
    const float* g = xyz + b*NN*3;
    const int* pm = g_perm + (b<<12);

    int   o[8];
    float sx[8], sy[8], sz[8], pd[8];
#pragma unroll
    for (int j=0;j<8;++j){
        int oj = pm[tid*8 + j];
        o[j] = oj;
        sx[j]=g[3*oj]; sy[j]=g[3*oj+1]; sz[j]=g[3*oj+2];
        pd[j]=1e10f;
    }
    u64 px[4], py[4], pz[4];
#pragma unroll
    for (int q=0;q<4;++q){
        PACK2(px[q], sx[2*q], sx[2*q+1]);
        PACK2(py[q], sy[2*q], sy[2*q+1]);
        PACK2(pz[q], sz[2*q], sz[2*q+1]);
    }
    // warp bounding sphere
    float mnx=sx[0],mxx=sx[0],mny=sy[0],mxy=sy[0],mnz=sz[0],mxz=sz[0];
#pragma unroll
    for (int j=1;j<8;++j){
        mnx=fminf(mnx,sx[j]); mxx=fmaxf(mxx,sx[j]);
        mny=fminf(mny,sy[j]); mxy=fmaxf(mxy,sy[j]);
        mnz=fminf(mnz,sz[j]); mxz=fmaxf(mxz,sz[j]);
    }
#pragma unroll
    for (int off=16; off; off>>=1){
        mnx=fminf(mnx,__shfl_xor_sync(0xffffffffu,mnx,off));
        mxx=fmaxf(mxx,__shfl_xor_sync(0xffffffffu,mxx,off));
        mny=fminf(mny,__shfl_xor_sync(0xffffffffu,mny,off));
        mxy=fmaxf(mxy,__shfl_xor_sync(0xffffffffu,mxy,off));
        mnz=fminf(mnz,__shfl_xor_sync(0xffffffffu,mnz,off));
        mxz=fmaxf(mxz,__shfl_xor_sync(0xffffffffu,mxz,off));
    }
    float mx_=(mnx+mxx)*0.5f, my_=(mny+mxy)*0.5f, mz_=(mnz+mxz)*0.5f;
    float rr = 0.f;
#pragma unroll
    for (int j=0;j<8;++j){
        float dx=sx[j]-mx_, dy=sy[j]-my_, dz=sz[j]-mz_;
        rr = fmaxf(rr, dx*dx+dy*dy+dz*dz);
    }
#pragma unroll
    for (int off=16; off; off>>=1)
        rr = fmaxf(rr, __shfl_xor_sync(0xffffffffu, rr, off));
    float r = sqrtf(rr)*1.001f + 1e-7f;

    float T = 3.0e38f;      // first step always refreshes
    u64 wkey = 0;

    if (tid==0){
        g_fps[b*NPOINT] = 0;
        out[b*3*NPOINT + 0*NPOINT] = g[0];
        out[b*3*NPOINT + 1*NPOINT] = g[1];
        out[b*3*NPOINT + 2*NPOINT] = g[2];
    }
    float cx=g[0], cy=g[1], cz=g[2];

    for (int t=1; t<NPOINT; ++t){
        // warp-uniform skip test (conservative; any precision is safe here)
        float ax=cx-mx_, ay=cy-my_, az=cz-mz_;
        float q2 = ax*ax + ay*ay + az*az;
        if (q2*0.998f < T){
            // refresh: bit-exact reference distance order
            float nx=__int_as_float(__float_as_int(cx)^0x80000000);
            float ny=__int_as_float(__float_as_int(cy)^0x80000000);
            float nz=__int_as_float(__float_as_int(cz)^0x80000000);
            u64 ncx,ncy,ncz; PACK2(ncx,nx,nx); PACK2(ncy,ny,ny); PACK2(ncz,nz,nz);
#pragma unroll
            for (int q=0;q<4;++q){
                u64 dx,dy,dz,s01,dv;
                ADD2(dx,px[q],ncx); ADD2(dy,py[q],ncy); ADD2(dz,pz[q],ncz);
                MUL2(dx,dx,dx); MUL2(dy,dy,dy); MUL2(dz,dz,dz);
                ADD2(s01,dx,dy); ADD2(dv,s01,dz);
                float d0,d1; UNPK2(d0,d1,dv);
                pd[2*q]   = fminf(pd[2*q],   d0);
                pd[2*q+1] = fminf(pd[2*q+1], d1);
            }
            float bv = fmaxf(fmaxf(fmaxf(pd[0],pd[1]),fmaxf(pd[2],pd[3])),
                             fmaxf(fmaxf(pd[4],pd[5]),fmaxf(pd[6],pd[7])));
            unsigned vb   = (unsigned)__float_as_int(bv);
            unsigned vmax = __reduce_max_sync(0xffffffffu, vb);
            unsigned lo = 0u;
            if (vb == vmax){
                int bj = 0x7fffffff;
#pragma unroll
                for (int j=0;j<8;++j) if (pd[j]==bv) bj = min(bj, o[j]);
                lo = ~(unsigned)bj;
            }
            unsigned lmax = __reduce_max_sync(0xffffffffu, lo);
            wkey = ((u64)vmax<<32) | lmax;
            float wm = __int_as_float((int)vmax);
            float s  = sqrtf(wm);
            float tt = r + s;
            T = tt*tt*1.004f;
        }
        if (lane==0) swk[t&1][wid] = wkey;
        __syncthreads();

        u64 k = swk[t&1][lane&15];
        unsigned hi  = (unsigned)(k>>32);
        unsigned hm  = __reduce_max_sync(0xffffffffu, hi);
        unsigned lo2 = (hi==hm) ? (unsigned)k : 0u;
        unsigned lm  = __reduce_max_sync(0xffffffffu, lo2);
        int far = (int)(~lm);
        cx = __ldg(&g[3*far]); cy = __ldg(&g[3*far+1]); cz = __ldg(&g[3*far+2]);
        if (tid==0){
            g_fps[b*NPOINT + t] = far;
            out[b*3*NPOINT + 0*NPOINT + t] = cx;
            out[b*3*NPOINT + 1*NPOINT + t] = cy;
            out[b*3*NPOINT + 2*NPOINT + t] = cz;
        }
    }
}

// ---------------- kNN: one warp per query, streaming top-32 -------------
__device__ __forceinline__ void warp_argmax(float& mv, int& ml){
#pragma unroll
    for (int off=16; off; off>>=1){
        float ov = __shfl_xor_sync(0xffffffffu, mv, off);
        int   ol = __shfl_xor_sync(0xffffffffu, ml, off);
        if (ov > mv || (ov == mv && ol < ml)){ mv = ov; ml = ol; }
    }
}

__global__ void __launch_bounds__(256)
knn_kernel(const float* __restrict__ xyz){
    int wid  = threadIdx.x >> 5, lane = threadIdx.x & 31;
    int b = blockIdx.x >> 7;
    int s = ((blockIdx.x & 127) << 3) + wid;
    const float* xb  = xyz + b*NN*3;
    const float* pnb = g_pn + b*NN;

    int qidx = g_fps[b*NPOINT + s];
    float qx = xb[3*qidx], qy = xb[3*qidx+1], qz = xb[3*qidx+2];
    float qn = pnb[qidx];

    float v; int vi;
    {
        int j = lane;
        float dot = __fadd_rn(__fadd_rn(__fmul_rn(qx,xb[3*j]), __fmul_rn(qy,xb[3*j+1])),
                              __fmul_rn(qz,xb[3*j+2]));
        v  = __fadd_rn(__fadd_rn(__fmul_rn(-2.f,dot), qn), pnb[j]);
        vi = j;
    }
    float mv = v; int ml = lane;
    warp_argmax(mv, ml);
    float tau = mv; int maxlane = ml;

    for (int base=32; base<NN; base+=32){
        int j = base + lane;
        float dot = __fadd_rn(__fadd_rn(__fmul_rn(qx,xb[3*j]), __fmul_rn(qy,xb[3*j+1])),
                              __fmul_rn(qz,xb[3*j+2]));
        float cand = __fadd_rn(__fadd_rn(__fmul_rn(-2.f,dot), qn), pnb[j]);
        unsigned mask = __ballot_sync(0xffffffffu, cand < tau);
        while (mask){
            int src  = __ffs(mask) - 1;
            float cv = __shfl_sync(0xffffffffu, cand, src);
            if (lane == maxlane){ v = cv; vi = base + src; }
            if (lane == src) cand = 3.0e38f;
            mv = v; ml = lane;
            warp_argmax(mv, ml);
            tau = mv; maxlane = ml;
            mask = __ballot_sync(0xffffffffu, cand < tau);
        }
    }
    g_knn[(b*NPOINT + s)*KK + lane] = vi;
}

// ---------------- gather-count histogram (int atomics: deterministic) ----
__global__ void hist_kernel(){
    int e = blockIdx.x*blockDim.x + threadIdx.x;
    if (e < RR){
        int b = e >> 15;
        atomicAdd(&g_cnt[(b<<12) + g_knn[e]], 1);
    }
}

// ---------------- conv on UNIQUE rows ----------------
#define CONV_SMEM ((64*72 + 128*65)*4)

template<int MODE>
__global__ void __launch_bounds__(128)
conv_kernel(int i0, int i1, const float* __restrict__ W,
            const float* __restrict__ features, int oid, int affA, int affB){
    extern __shared__ float sm[];
    float* Wt = sm;            // [64][72]
    float* As = sm + 64*72;    // [128][65]

    const int tid = threadIdx.x;
    const int rbase = blockIdx.x * 128;

    for (int i = tid; i < 4096; i += 128){
        int o = i >> 6, c = i & 63;
        Wt[c*72 + o] = W[i];
    }
    for (int i = tid; i < 8192; i += 128){
        int row = i >> 6, c = i & 63;
        int r = rbase + row;
        float vv;
        if (MODE == 0){
            vv = features[(size_t)r*CC + c];
        } else {
            float x0 = g_buf[i0][(size_t)r*CC + c];
            float a1 = g_aff[affB][0][c], d1 = g_aff[affB][1][c];
            if (MODE == 1){
                vv = leaky(fmaf(a1, x0, d1));
            } else {
                float x1 = g_buf[i1][(size_t)r*CC + c];
                float a0 = g_aff[affA][0][c], d0 = g_aff[affA][1][c];
                vv = leaky(fmaf(a1, x0, d1) + leaky(fmaf(a0, x1, d0)));
            }
        }
        As[row*65 + c] = vv;
    }
    __syncthreads();

    const int ry = tid >> 3, ox = tid & 7;
    const int r0 = ry*8, o0 = ox*8;

    float acc[8][8];
#pragma unroll
    for (int j=0;j<8;++j)
#pragma unroll
        for (int o=0;o<8;++o) acc[j][o] = 0.f;

#pragma unroll 2
    for (int c=0;c<CC;++c){
        float4 w0 = *(const float4*)&Wt[c*72 + o0];
        float4 w1 = *(const float4*)&Wt[c*72 + o0 + 4];
        float av[8];
#pragma unroll
        for (int j=0;j<8;++j) av[j] = As[(r0+j)*65 + c];
#pragma unroll
        for (int j=0;j<8;++j){
            acc[j][0] = fmaf(av[j], w0.x, acc[j][0]);
            acc[j][1] = fmaf(av[j], w0.y, acc[j][1]);
            acc[j][2] = fmaf(av[j], w0.z, acc[j][2]);
            acc[j][3] = fmaf(av[j], w0.w, acc[j][3]);
            acc[j][4] = fmaf(av[j], w1.x, acc[j][4]);
            acc[j][5] = fmaf(av[j], w1.y, acc[j][5]);
            acc[j][6] = fmaf(av[j], w1.z, acc[j][6]);
            acc[j][7] = fmaf(av[j], w1.w, acc[j][7]);
        }
    }

    float* outb = g_buf[oid];
    float cw[8];
#pragma unroll
    for (int j=0;j<8;++j){
        size_t r = (size_t)(rbase + r0 + j);
        cw[j] = (float)__ldg(&g_cnt[r]);
        *(float4*)&outb[r*CC + o0]     = make_float4(acc[j][0],acc[j][1],acc[j][2],acc[j][3]);
        *(float4*)&outb[r*CC + o0 + 4] = make_float4(acc[j][4],acc[j][5],acc[j][6],acc[j][7]);
    }

    __syncthreads();
    float* sred1 = sm;
    float* sred2 = sm + 1024;
#pragma unroll
    for (int o=0;o<8;++o){
        float s1 = 0.f, s2 = 0.f;
#pragma unroll
        for (int j=0;j<8;++j){ s1 += cw[j]*acc[j][o]; s2 += cw[j]*acc[j][o]*acc[j][o]; }
        sred1[ry*64 + o0 + o] = s1;
        sred2[ry*64 + o0 + o] = s2;
    }
    __syncthreads();
    if (tid < CC){
        float s1=0.f, s2=0.f;
#pragma unroll
        for (int j=0;j<16;++j){ s1 += sred1[j*64 + tid]; s2 += sred2[j*64 + tid]; }
        g_part[blockIdx.x][0][tid] = s1;
        g_part[blockIdx.x][1][tid] = s2;
    }
}

// ---------------- BN affine finalize ----------------
__global__ void __launch_bounds__(256)
affine_kernel(int stage, const float* __restrict__ gam, const float* __restrict__ bet){
    __shared__ float r1[256], r2[256];
    int c = blockIdx.x, t = threadIdx.x;
    float s1 = g_part[t][0][c];
    float s2 = g_part[t][1][c];
    r1[t]=s1; r2[t]=s2; __syncthreads();
    for (int off=128; off; off>>=1){
        if (t < off){ r1[t]+=r1[t+off]; r2[t]+=r2[t+off]; }
        __syncthreads();
    }
    if (t==0){
        float inv  = 1.f/(float)RR;
        float mean = r1[0]*inv;
        float var  = r2[0]*inv - mean*mean;
        float a    = gam[c]/sqrtf(var + EPSBN);
        g_aff[stage][0][c] = a;
        g_aff[stage][1][c] = bet[c] - a*mean;
    }
}

// ---------------- x1 on unique rows (pointwise) ----------------
__global__ void __launch_bounds__(256)
x1_kernel(){
    int i = blockIdx.x*blockDim.x + threadIdx.x;
    int c = i & 63;
    float a0=g_aff[0][0][c], d0=g_aff[0][1][c];
    float a2=g_aff[2][0][c], d2=g_aff[2][1][c];
    float a4=g_aff[4][0][c], d4=g_aff[4][1][c];
    float xt = leaky(fmaf(a0, g_buf[0][i], d0));
    float x0 = leaky(fmaf(a2, g_buf[2][i], d2) + xt);
    float x1 = leaky(fmaf(a4, g_buf[3][i], d4) + x0);
    g_buf[1][i] = x1;
}

// ---------------- final: gather x1 + max over K ----------------
__global__ void __launch_bounds__(256)
final_kernel(float* __restrict__ out){
    __shared__ float sfin[4][CC];
    int m = blockIdx.x;
    int tid = threadIdx.x;
    int kk = tid >> 6, c = tid & 63;
    int b = m >> 10, s = m & 1023;
    const int* kn = &g_knn[m*KK];
    const float* x1 = g_buf[1];
    size_t bbase = (size_t)b << 12;
    float vmax = -3.4e38f;
#pragma unroll
    for (int j=0;j<8;++j){
        int idx = __ldg(&kn[kk*8 + j]);
        vmax = fmaxf(vmax, x1[(bbase + idx)*CC + c]);
    }
    sfin[kk][c] = vmax;
    __syncthreads();
    if (tid < CC){
        float v = fmaxf(fmaxf(sfin[0][tid], sfin[1][tid]),
                        fmaxf(sfin[2][tid], sfin[3][tid]));
        out[BB*3*NPOINT + (b*CC + tid)*NPOINT + s] = v;
    }
}

// ---------------- launch ----------------
extern "C" void kernel_launch(void* const* d_in, const int* in_sizes, int n_in,
                              void* d_out, int out_size){
    (void)n_in; (void)out_size;
    const float* xyz  = (const float*)d_in[0];
    const float* feat = (const float*)d_in[1];
    const float *w[5], *gam[5], *bet[5];
    if (in_sizes[3] == CC*CC){
        const int wi[5]={2,3,4,5,6}, gi[5]={12,13,14,15,16}, bi[5]={17,18,19,20,21};
        for (int i=0;i<5;++i){ w[i]=(const float*)d_in[wi[i]];
                               gam[i]=(const float*)d_in[gi[i]];
                               bet[i]=(const float*)d_in[bi[i]]; }
    } else {
        const int wi[5]={2,6,10,14,18}, gi[5]={4,8,12,16,20}, bi[5]={5,9,13,17,21};
        for (int i=0;i<5;++i){ w[i]=(const float*)d_in[wi[i]];
                               gam[i]=(const float*)d_in[gi[i]];
                               bet[i]=(const float*)d_in[bi[i]]; }
    }
    float* out = (float*)d_out;

    cudaFuncSetAttribute(conv_kernel<0>, cudaFuncAttributeMaxDynamicSharedMemorySize, CONV_SMEM);
    cudaFuncSetAttribute(conv_kernel<1>, cudaFuncAttributeMaxDynamicSharedMemorySize, CONV_SMEM);
    cudaFuncSetAttribute(conv_kernel<2>, cudaFuncAttributeMaxDynamicSharedMemorySize, CONV_SMEM);

    prep_kernel<<<128,256>>>(xyz);
    cellkey_kernel<<<128,256>>>(xyz);
    scan_kernel<<<BB,512>>>();
    scatter_kernel<<<128,256>>>();
    fps_kernel<<<BB,512>>>(xyz, out);
    knn_kernel<<<1024,256>>>(xyz);
    hist_kernel<<<256,1024>>>();

    conv_kernel<0><<<256,128,CONV_SMEM>>>(0,0,w[0],feat,0,0,0);
    affine_kernel<<<64,256>>>(0, gam[0], bet[0]);
    conv_kernel<1><<<256,128,CONV_SMEM>>>(0,0,w[1],feat,1,0,0);
    affine_kernel<<<64,256>>>(1, gam[1], bet[1]);
    conv_kernel<1><<<256,128,CONV_SMEM>>>(1,0,w[2],feat,2,0,1);
    affine_kernel<<<64,256>>>(2, gam[2], bet[2]);
    conv_kernel<2><<<256,128,CONV_SMEM>>>(2,0,w[3],feat,1,0,2);
    affine_kernel<<<64,256>>>(3, gam[3], bet[3]);
    conv_kernel<1><<<256,128,CONV_SMEM>>>(1,0,w[4],feat,3,0,3);
    affine_kernel<<<64,256>>>(4, gam[4], bet[4]);

    x1_kernel<<<8192,256>>>();
    final_kernel<<<MM,256>>>(out);
}